// round 11
// baseline (speedup 1.0000x reference)
#include <cuda_runtime.h>
#include <cuda_bf16.h>

// p1, p2: [B=2, C=32, D=96, H=96, W=96] fp32
// pool to S=8 (cells 12^3), L = 512 tokens, C = 32 channels.
// loss = (1/(L^2 B)) * sum_b [ ||Ga||F^2 + ||Gb||F^2 - 2||Gx||F^2 ]
// with Ga = Ua^T Ua, Gb = Ub^T Ub, Gx = Ua^T Ub over unit-normalized tokens.
//
// Single fused kernel: pooling blocks take per-chunk tickets; the last
// contributor of each 32-token chunk computes that chunk's partial Grams
// inline (overlapped with remaining pooling). A global done-counter gates
// the final reduction, so the post-pool tail is ~2us.

#define BATCH 2
#define CH    32
#define DIM   96
#define LTOK  512
#define BLK   12
#define EPS   1e-8f
#define LSTR  33
#define NCHUNK 32          // 2 batches x 8 pd x 2 ph-groups
#define CONTRIB 256        // 2 tensors x 32 ch x 4 ph per chunk

// pooled tokens token-major: [tensor(2)][b(2)][l(512)][c(32)]
__device__ float g_pooled[2 * BATCH * LTOK * CH];
// partial Grams: [b(2)][g(3: aa, bb, ab)][i(32)][j(32)]  (zero-init at load;
// re-zeroed by the finalizer each call for graph replay)
__device__ float g_gram[BATCH * 3 * CH * CH];
__device__ unsigned int g_chunk_cnt[NCHUNK];
__device__ unsigned int g_done;

__global__ __launch_bounds__(96, 16)
void fused_kernel(const float* __restrict__ p1,
                  const float* __restrict__ p2,
                  float* __restrict__ out)
{
    const int bid = blockIdx.x;
    const int ph = bid & 7;
    const int pd = (bid >> 3) & 7;
    const int c  = (bid >> 6) & 31;
    const int b  = (bid >> 11) & 1;
    const int t  = bid >> 12;

    const float* __restrict__ in = (t == 0) ? p1 : p2;

    const int tid = threadIdx.x;
    const int f4  = tid % 24;   // w = 4*f4
    const int rs  = tid / 24;   // 0..3 -> d in [3rs, 3rs+3)

    // ---------------- Phase 1: pooling (HBM-bound, 453 MB stream) ----------
    const float* __restrict__ base =
        in + ((size_t)(b * CH + c)) * (DIM * DIM * DIM)
           + (size_t)(pd * BLK + 3 * rs) * (DIM * DIM)
           + (size_t)ph * BLK * DIM
           + f4 * 4;

    float acc = 0.0f;
    #pragma unroll
    for (int d2 = 0; d2 < 3; ++d2) {
        #pragma unroll
        for (int h = 0; h < 12; ++h) {
            const float4 v = __ldcs(reinterpret_cast<const float4*>(
                base + d2 * (DIM * DIM) + h * DIM));
            acc += (v.x + v.y) + (v.z + v.w);
        }
    }

    __shared__ float sh[96];
    sh[tid] = acc;
    __syncthreads();

    if (tid < 8) {
        float s = 0.0f;
        #pragma unroll
        for (int r2 = 0; r2 < 4; ++r2)
            #pragma unroll
            for (int j = 0; j < 3; ++j)
                s += sh[r2 * 24 + tid * 3 + j];
        const int l = pd * 64 + ph * 8 + tid;
        g_pooled[(((size_t)t * BATCH + b) * LTOK + l) * CH + c] =
            s * (1.0f / (BLK * BLK * BLK));
        __threadfence();   // release pooled writes (per writing thread)
    }
    __syncthreads();

    // ---------------- Phase 2: chunk ticket -------------------------------
    const int phg = ph >> 2;
    const int cid = b * 16 + pd * 2 + phg;   // 32 chunks
    const int l0  = pd * 64 + phg * 32;      // first token of chunk

    __shared__ unsigned int s_ticket;
    if (tid == 0) s_ticket = atomicAdd(&g_chunk_cnt[cid], 1u);
    __syncthreads();
    if (s_ticket != CONTRIB - 1) return;     // not the last contributor

    // ---------------- Phase 3: this chunk's partial Grams -----------------
    __threadfence();                          // acquire all contributors

    __shared__ float sh_tok[2 * CH * LSTR];   // [t][c][l], stride 33
    for (int idx = tid; idx < 2 * 32 * CH; idx += 96) {
        const int tt = idx >> 10;
        const int l  = (idx >> 5) & 31;
        const int cc = idx & 31;
        sh_tok[tt * CH * LSTR + cc * LSTR + l] =
            __ldcg(&g_pooled[(((size_t)tt * BATCH + b) * LTOK + l0 + l) * CH + cc]);
    }
    __syncthreads();

    // normalize the 64 token columns (eps never binds for this data;
    // fmaxf keeps exact reference semantics in the degenerate case)
    if (tid < 64) {
        const int tt = tid >> 5;
        const int l  = tid & 31;
        float* col = sh_tok + tt * CH * LSTR + l;
        float s = 0.0f;
        #pragma unroll
        for (int cc = 0; cc < CH; ++cc) {
            const float v = col[cc * LSTR];
            s += v * v;
        }
        const float r = 1.0f / sqrtf(fmaxf(s, EPS));
        #pragma unroll
        for (int cc = 0; cc < CH; ++cc)
            col[cc * LSTR] *= r;
    }
    __syncthreads();

    // 3 warps = 3 Grams (aa, bb, ab); lane = output row i (channel),
    // 8-column register groups; Q reads are warp-broadcast LDS.
    {
        const int g = tid >> 5;   // 0..2
        const int i = tid & 31;
        const float* __restrict__ P = sh_tok + ((g == 1) ? CH * LSTR : 0);
        const float* __restrict__ Q = sh_tok + ((g == 0) ? 0 : CH * LSTR);
        float* __restrict__ dst = g_gram + (((b * 3 + g) << 10) + (i << 5));

        #pragma unroll
        for (int jg = 0; jg < 4; ++jg) {
            float a0 = 0, a1 = 0, a2 = 0, a3 = 0, a4 = 0, a5 = 0, a6 = 0, a7 = 0;
            #pragma unroll
            for (int l = 0; l < 32; ++l) {
                const float p = P[i * LSTR + l];
                const float* q = Q + (jg * 8) * LSTR + l;
                a0 += p * q[0 * LSTR];  a1 += p * q[1 * LSTR];
                a2 += p * q[2 * LSTR];  a3 += p * q[3 * LSTR];
                a4 += p * q[4 * LSTR];  a5 += p * q[5 * LSTR];
                a6 += p * q[6 * LSTR];  a7 += p * q[7 * LSTR];
            }
            atomicAdd(&dst[jg * 8 + 0], a0);  atomicAdd(&dst[jg * 8 + 1], a1);
            atomicAdd(&dst[jg * 8 + 2], a2);  atomicAdd(&dst[jg * 8 + 3], a3);
            atomicAdd(&dst[jg * 8 + 4], a4);  atomicAdd(&dst[jg * 8 + 5], a5);
            atomicAdd(&dst[jg * 8 + 6], a6);  atomicAdd(&dst[jg * 8 + 7], a7);
        }
    }

    // ---------------- Phase 4: done ticket + finalize ----------------------
    __syncthreads();
    if (tid == 0) {
        g_chunk_cnt[cid] = 0u;               // reset for next replay
        __threadfence();                      // release gram atomics
        s_ticket = atomicAdd(&g_done, 1u);
    }
    __syncthreads();
    if (s_ticket != NCHUNK - 1) return;      // not the last chunk

    __threadfence();                          // acquire all gram updates

    float local = 0.0f;
    for (int i2 = tid; i2 < BATCH * 3 * CH * CH; i2 += 96) {
        const int gg = (i2 >> 10) % 3;
        const float v = __ldcg(&g_gram[i2]);
        local += ((gg == 2) ? -2.0f : 1.0f) * v * v;
    }
    #pragma unroll
    for (int off = 16; off > 0; off >>= 1)
        local += __shfl_xor_sync(0xFFFFFFFFu, local, off);

    __shared__ float wsum[3];
    if ((tid & 31) == 0) wsum[tid >> 5] = local;
    __syncthreads();
    if (tid == 0) {
        const float s = wsum[0] + wsum[1] + wsum[2];
        out[0] = s * (1.0f / ((float)LTOK * (float)LTOK * (float)BATCH));
        g_done = 0u;                          // reset for next replay
    }
    __syncthreads();                          // reads done before re-zeroing
    for (int i2 = tid; i2 < BATCH * 3 * CH * CH; i2 += 96)
        g_gram[i2] = 0.0f;
}

// ---------------------------------------------------------------------------
extern "C" void kernel_launch(void* const* d_in, const int* in_sizes, int n_in,
                              void* d_out, int out_size)
{
    const float* p1 = (const float*)d_in[0];
    const float* p2 = (const float*)d_in[1];
    float* out = (float*)d_out;

    fused_kernel<<<8192, 96>>>(p1, p2, out);  // 2*2*32*8*8 blocks
}